// round 9
// baseline (speedup 1.0000x reference)
#include <cuda_runtime.h>
#include <cuda_fp16.h>

#define NMAX 100000
#define EPSF 1e-5f

// Fused q/k/v scratch, fp16. Row = 192 halves = 384 bytes (3 x 128B lines:
// q at +0, k at +128B, v at +256B -> each slice is one aligned 128B line).
__device__ __half g_qkv[NMAX * 192];
__device__ __half g_Wh[192 * 64];     // B[n=o3][k=c] fp16 (row-major = mma col B)
__device__ float  g_bias[192];

__device__ __forceinline__ float4 ldg_h4(size_t row, int part, int sub) {
    const __half2* base = (const __half2*)g_qkv;
    uint2 u = *(const uint2*)(base + row * 96 + part + sub * 2);
    __half2 a = *(__half2*)&u.x, b = *(__half2*)&u.y;
    float2 fa = __half22float2(a), fb = __half22float2(b);
    return make_float4(fa.x, fa.y, fb.x, fb.y);
}

// ---------------------------------------------------------------------------
// Folded constants, staged on device then copied into __constant__.
// ---------------------------------------------------------------------------
struct CParams {
    float4 w1[128];                         // w_w1 [o][4g..4g+3]
    float4 A[16];                           // bn1 scale folded
    float4 T0[16], T1[16], T2[16], TB[16];  // A*pw2 cols, A*pb2 + b1
    float4 R0[16], R1[16], R2[16], RB[16];  // raw pw2 cols, raw pb2
    float a2[8], c2f[8];
    float w2[64];
    float wb2[8];
    float fw1[9], fb1[3];
    float pad[4];
};
__device__ CParams g_stage;
__constant__ CParams c_P;

__global__ void prep_kernel(
    const float* __restrict__ Wq, const float* __restrict__ bq,
    const float* __restrict__ Wk, const float* __restrict__ bk,
    const float* __restrict__ Wv, const float* __restrict__ bv,
    const float* __restrict__ pw1, const float* __restrict__ pb1,
    const float* __restrict__ pbng, const float* __restrict__ pbnb,
    const float* __restrict__ pbnm, const float* __restrict__ pbnv,
    const float* __restrict__ pw2, const float* __restrict__ pb2,
    const float* __restrict__ bn1g, const float* __restrict__ bn1b,
    const float* __restrict__ bn1m, const float* __restrict__ bn1v,
    const float* __restrict__ w1,  const float* __restrict__ wb1,
    const float* __restrict__ bn2g, const float* __restrict__ bn2b,
    const float* __restrict__ bn2m, const float* __restrict__ bn2v,
    const float* __restrict__ w2,  const float* __restrict__ wb2)
{
    int t = threadIdx.x;  // 192 threads
    if (t < 64) {
        float a  = bn1g[t] * rsqrtf(bn1v[t] + EPSF);
        float b1 = bn1b[t] - bn1m[t] * a;
        float r0 = pw2[t * 3 + 0], r1 = pw2[t * 3 + 1], r2 = pw2[t * 3 + 2];
        float rb = pb2[t];
        ((float*)g_stage.A )[t] = a;
        ((float*)g_stage.T0)[t] = a * r0;
        ((float*)g_stage.T1)[t] = a * r1;
        ((float*)g_stage.T2)[t] = a * r2;
        ((float*)g_stage.TB)[t] = a * rb + b1;
        ((float*)g_stage.R0)[t] = r0;
        ((float*)g_stage.R1)[t] = r1;
        ((float*)g_stage.R2)[t] = r2;
        ((float*)g_stage.RB)[t] = rb;
        g_stage.w2[t] = w2[t];
    }
    for (int i = t; i < 512; i += 192) ((float*)g_stage.w1)[i] = w1[i];
    if (t < 8) {
        float a2 = bn2g[t] * rsqrtf(bn2v[t] + EPSF);
        g_stage.a2[t]  = a2;
        g_stage.c2f[t] = a2 * wb1[t] + (bn2b[t] - bn2m[t] * a2);
        g_stage.wb2[t] = wb2[t];
    }
    if (t < 3) {
        float pa = pbng[t] * rsqrtf(pbnv[t] + EPSF);
        g_stage.fw1[t * 3 + 0] = pa * pw1[t * 3 + 0];
        g_stage.fw1[t * 3 + 1] = pa * pw1[t * 3 + 1];
        g_stage.fw1[t * 3 + 2] = pa * pw1[t * 3 + 2];
        g_stage.fb1[t] = pa * pb1[t] + (pbnb[t] - pbnm[t] * pa);
    }
    // weights -> fp16 [o3][c], biases fp32
    g_bias[t] = (t < 64) ? bq[t] : (t < 128) ? bk[t - 64] : bv[t - 128];
    for (int i = t; i < 192 * 64; i += 192) {
        int o = i >> 6, c = i & 63;
        float w = (o < 64) ? Wq[o * 64 + c]
                : (o < 128) ? Wk[(o - 64) * 64 + c]
                            : Wv[(o - 128) * 64 + c];
        g_Wh[i] = __float2half_rn(w);
    }
}

// ---------------------------------------------------------------------------
// Kernel A: q/k/v projection via HMMA mma.sync m16n8k16 (fp16 in, fp32 acc).
// Block = 64 points x 192 outputs. 8 warps: warp w -> m-tile (w&3), n-half
// (w>>2) covering 12 n-tiles of 8.
// ---------------------------------------------------------------------------
__device__ __forceinline__ void mma16816(float* c, unsigned a0, unsigned a1,
                                         unsigned a2, unsigned a3,
                                         unsigned b0, unsigned b1) {
    asm volatile(
        "mma.sync.aligned.m16n8k16.row.col.f32.f16.f16.f32 "
        "{%0,%1,%2,%3}, {%4,%5,%6,%7}, {%8,%9}, {%0,%1,%2,%3};"
        : "+f"(c[0]), "+f"(c[1]), "+f"(c[2]), "+f"(c[3])
        : "r"(a0), "r"(a1), "r"(a2), "r"(a3), "r"(b0), "r"(b1));
}

__global__ __launch_bounds__(256) void proj3(const float* __restrict__ x, int N)
{
    __shared__ __align__(16) __half xh[64][72];    // x tile fp16, padded
    __shared__ __align__(16) __half wh[192][72];   // W fp16 [o][c], padded
    __shared__ float bsh[192];
    int t = threadIdx.x;
    int tile0 = blockIdx.x * 64;

    for (int i = t; i < 192 * 32; i += 256) {
        int row = i >> 5, cp = i & 31;
        *(unsigned*)&wh[row][cp * 2] = ((const unsigned*)g_Wh)[i];
    }
    if (t < 192) bsh[t] = g_bias[t];
    for (int i = t; i < 1024; i += 256) {
        int pl = i >> 4, c4 = (i & 15) * 4;
        int pt = tile0 + pl; pt = (pt < N) ? pt : N - 1;
        float4 v = *(const float4*)&x[(size_t)pt * 64 + c4];
        __half2 h0 = __floats2half2_rn(v.x, v.y);
        __half2 h1 = __floats2half2_rn(v.z, v.w);
        uint2 st; st.x = *(unsigned*)&h0; st.y = *(unsigned*)&h1;
        *(uint2*)&xh[pl][c4] = st;
    }
    __syncthreads();

    int warp = t >> 5, lane = t & 31;
    int mt = warp & 3, nh = warp >> 2;
    int gr = lane >> 2, gc = lane & 3;

    float acc[12][4];
    #pragma unroll
    for (int nt = 0; nt < 12; nt++)
        #pragma unroll
        for (int k = 0; k < 4; k++) acc[nt][k] = 0.f;

    #pragma unroll
    for (int ks = 0; ks < 4; ks++) {
        int kb = ks * 16 + 2 * gc;
        unsigned a0 = *(unsigned*)&xh[mt * 16 + gr][kb];
        unsigned a1 = *(unsigned*)&xh[mt * 16 + gr + 8][kb];
        unsigned a2 = *(unsigned*)&xh[mt * 16 + gr][kb + 8];
        unsigned a3 = *(unsigned*)&xh[mt * 16 + gr + 8][kb + 8];
        #pragma unroll
        for (int nt = 0; nt < 12; nt++) {
            int n = (nh * 12 + nt) * 8 + gr;
            unsigned b0 = *(unsigned*)&wh[n][kb];
            unsigned b1 = *(unsigned*)&wh[n][kb + 8];
            mma16816(acc[nt], a0, a1, a2, a3, b0, b1);
        }
    }

    int pt0 = tile0 + mt * 16 + gr;
    int pt1 = pt0 + 8;
    #pragma unroll
    for (int nt = 0; nt < 12; nt++) {
        int col = (nh * 12 + nt) * 8 + 2 * gc;
        float bx = bsh[col], by = bsh[col + 1];
        if (pt0 < N) {
            __half2 h = __floats2half2_rn(acc[nt][0] + bx, acc[nt][1] + by);
            *(unsigned*)&g_qkv[(size_t)pt0 * 192 + col] = *(unsigned*)&h;
        }
        if (pt1 < N) {
            __half2 h = __floats2half2_rn(acc[nt][2] + bx, acc[nt][3] + by);
            *(unsigned*)&g_qkv[(size_t)pt1 * 192 + col] = *(unsigned*)&h;
        }
    }
}

// ---------------------------------------------------------------------------
// Kernel B: fused attention. Block = 8 points, 128 threads, warp-local.
// ---------------------------------------------------------------------------
__global__ __launch_bounds__(128) void attn2(
    const float* __restrict__ p, const int* __restrict__ idx,
    float* __restrict__ out, int N)
{
    __shared__ __align__(16) float4 vbuf[8][16][16];
    __shared__ __align__(16) float  wex[8][16][12];
    __shared__ __align__(16) float  Hs[8][3][8];
    __shared__ float hs[8][16][4];
    __shared__ int   idxs[8][16];
    __shared__ float pns[8][4];

    int t = threadIdx.x, lane = t & 31, wid = t >> 5;
    int n0 = blockIdx.x * 8;

    int lpA = t >> 4, sub = t & 15;
    int nA  = n0 + lpA;
    int nAc = (nA < N) ? nA : N - 1;

    // prologue: indices, center coords, h-MLP
    int id0 = idx[(size_t)nAc * 16 + sub];
    id0 = (id0 < 0) ? 0 : ((id0 >= N) ? N - 1 : id0);
    idxs[lpA][sub] = id0;
    if (lane < 6) {
        int pp = wid * 2 + lane / 3, d = lane % 3;
        int np = n0 + pp; np = (np < N) ? np : N - 1;
        pns[pp][d] = p[(size_t)np * 3 + d];
    }
    __syncwarp();
    {
        float prx = p[(size_t)id0 * 3 + 0] - pns[lpA][0];
        float pry = p[(size_t)id0 * 3 + 1] - pns[lpA][1];
        float prz = p[(size_t)id0 * 3 + 2] - pns[lpA][2];
        hs[lpA][sub][0] = fmaxf(fmaf(prx, c_P.fw1[0], fmaf(pry, c_P.fw1[1], fmaf(prz, c_P.fw1[2], c_P.fb1[0]))), 0.f);
        hs[lpA][sub][1] = fmaxf(fmaf(prx, c_P.fw1[3], fmaf(pry, c_P.fw1[4], fmaf(prz, c_P.fw1[5], c_P.fb1[1]))), 0.f);
        hs[lpA][sub][2] = fmaxf(fmaf(prx, c_P.fw1[6], fmaf(pry, c_P.fw1[7], fmaf(prz, c_P.fw1[8], c_P.fb1[2]))), 0.f);
    }
    float4 Ac = c_P.A[sub];
    float4 T0 = c_P.T0[sub], T1 = c_P.T1[sub], T2 = c_P.T2[sub];
    float4 TBc = c_P.TB[sub];
    float4 xq4 = ldg_h4((size_t)nAc, 0, sub);
    float4 TBm = make_float4(TBc.x - Ac.x * xq4.x, TBc.y - Ac.y * xq4.y,
                             TBc.z - Ac.z * xq4.z, TBc.w - Ac.w * xq4.w);
    __syncwarp();

    // ---- Phase A: v = relu(A*xk + T.h + TBm) -> swizzled vbuf --------------
    #pragma unroll
    for (int j = 0; j < 16; j++) {
        int id = idxs[lpA][j];
        float h0 = hs[lpA][j][0], h1 = hs[lpA][j][1], h2 = hs[lpA][j][2];
        float4 xk4 = ldg_h4((size_t)id, 32, sub);
        float4 v;
        v.x = fmaxf(fmaf(Ac.x, xk4.x, fmaf(T2.x, h2, fmaf(T1.x, h1, fmaf(T0.x, h0, TBm.x)))), 0.f);
        v.y = fmaxf(fmaf(Ac.y, xk4.y, fmaf(T2.y, h2, fmaf(T1.y, h1, fmaf(T0.y, h0, TBm.y)))), 0.f);
        v.z = fmaxf(fmaf(Ac.z, xk4.z, fmaf(T2.z, h2, fmaf(T1.z, h1, fmaf(T0.z, h0, TBm.z)))), 0.f);
        v.w = fmaxf(fmaf(Ac.w, xk4.w, fmaf(T2.w, h2, fmaf(T1.w, h1, fmaf(T0.w, h0, TBm.w)))), 0.f);
        vbuf[lpA][j][(sub + j) & 15] = v;
    }
    __syncwarp();

    // ---- Phase B: 64->8 projection + BN2 + w2 + softmax --------------------
    int lpB = wid * 2 + (lane >> 4), jj = lane & 15;
    float acc[8];
    #pragma unroll
    for (int o = 0; o < 8; o++) acc[o] = 0.f;
    #pragma unroll
    for (int g = 0; g < 16; g++) {
        float4 v4 = vbuf[lpB][jj][(g + jj) & 15];
        #pragma unroll
        for (int o = 0; o < 8; o++) {
            float4 w = c_P.w1[o * 16 + g];
            acc[o] = fmaf(w.x, v4.x, fmaf(w.y, v4.y, fmaf(w.z, v4.z, fmaf(w.w, v4.w, acc[o]))));
        }
    }
    float y[8], z[8];
    #pragma unroll
    for (int o = 0; o < 8; o++)
        y[o] = fmaxf(fmaf(c_P.a2[o], acc[o], c_P.c2f[o]), 0.f);
    #pragma unroll
    for (int u = 0; u < 8; u++) {
        float s = c_P.wb2[u];
        #pragma unroll
        for (int o = 0; o < 8; o++) s = fmaf(y[o], c_P.w2[u * 8 + o], s);
        z[u] = s;
    }
    float e[8];
    #pragma unroll
    for (int u = 0; u < 8; u++) {
        float m = z[u];
        m = fmaxf(m, __shfl_xor_sync(0xffffffffu, m, 1));
        m = fmaxf(m, __shfl_xor_sync(0xffffffffu, m, 2));
        m = fmaxf(m, __shfl_xor_sync(0xffffffffu, m, 4));
        m = fmaxf(m, __shfl_xor_sync(0xffffffffu, m, 8));
        float ev = __expf(z[u] - m);
        float s = ev;
        s += __shfl_xor_sync(0xffffffffu, s, 1);
        s += __shfl_xor_sync(0xffffffffu, s, 2);
        s += __shfl_xor_sync(0xffffffffu, s, 4);
        s += __shfl_xor_sync(0xffffffffu, s, 8);
        e[u] = ev * __frcp_rn(s);
    }
    *(float4*)&wex[lpB][jj][0] = make_float4(e[0], e[1], e[2], e[3]);
    *(float4*)&wex[lpB][jj][4] = make_float4(e[4], e[5], e[6], e[7]);
    __syncwarp();

    // ---- H[u] = sum_j h_j * wex_j[u]  (per point, 3x8 values) --------------
    if (sub < 8) {
        float H0 = 0.f, H1 = 0.f, H2 = 0.f;
        #pragma unroll
        for (int j = 0; j < 16; j++) {
            float w = wex[lpA][j][sub];
            H0 = fmaf(hs[lpA][j][0], w, H0);
            H1 = fmaf(hs[lpA][j][1], w, H1);
            H2 = fmaf(hs[lpA][j][2], w, H2);
        }
        Hs[lpA][0][sub] = H0;
        Hs[lpA][1][sub] = H1;
        Hs[lpA][2][sub] = H2;
    }
    __syncwarp();

    // ---- Phase 2: out_c = base_c + sum_j xv_jc * wex_j[c&7] ----------------
    float4 q0 = c_P.R0[sub], q1 = c_P.R1[sub], q2 = c_P.R2[sub], qb = c_P.RB[sub];
    int u0 = (sub & 1) * 4;
    float4 H0v = *(const float4*)&Hs[lpA][0][u0];
    float4 H1v = *(const float4*)&Hs[lpA][1][u0];
    float4 H2v = *(const float4*)&Hs[lpA][2][u0];
    float bx = fmaf(q0.x, H0v.x, fmaf(q1.x, H1v.x, fmaf(q2.x, H2v.x, qb.x)));
    float by = fmaf(q0.y, H0v.y, fmaf(q1.y, H1v.y, fmaf(q2.y, H2v.y, qb.y)));
    float bz = fmaf(q0.z, H0v.z, fmaf(q1.z, H1v.z, fmaf(q2.z, H2v.z, qb.z)));
    float bw = fmaf(q0.w, H0v.w, fmaf(q1.w, H1v.w, fmaf(q2.w, H2v.w, qb.w)));

    float ox = 0.f, oy = 0.f, oz = 0.f, ow = 0.f;
    #pragma unroll
    for (int j = 0; j < 16; j++) {
        int id = idxs[lpA][j];
        float4 xv4 = ldg_h4((size_t)id, 64, sub);
        float4 wn4 = *(const float4*)&wex[lpA][j][u0];
        ox = fmaf(xv4.x, wn4.x, ox);
        oy = fmaf(xv4.y, wn4.y, oy);
        oz = fmaf(xv4.z, wn4.z, oz);
        ow = fmaf(xv4.w, wn4.w, ow);
    }
    if (nA < N)
        *(float4*)&out[(size_t)nA * 64 + sub * 4] =
            make_float4(ox + bx, oy + by, oz + bz, ow + bw);
}

// ---------------------------------------------------------------------------
extern "C" void kernel_launch(void* const* d_in, const int* in_sizes, int n_in,
                              void* d_out, int out_size)
{
    const float* p   = (const float*)d_in[0];
    const float* x   = (const float*)d_in[1];
    const int* idx   = (const int*)d_in[2];
    const float* Wq  = (const float*)d_in[3];
    const float* bq  = (const float*)d_in[4];
    const float* Wk  = (const float*)d_in[5];
    const float* bk  = (const float*)d_in[6];
    const float* Wv  = (const float*)d_in[7];
    const float* bv  = (const float*)d_in[8];
    const float* pw1 = (const float*)d_in[9];
    const float* pb1 = (const float*)d_in[10];
    const float* pbng = (const float*)d_in[11];
    const float* pbnb = (const float*)d_in[12];
    const float* pbnm = (const float*)d_in[13];
    const float* pbnv = (const float*)d_in[14];
    const float* pw2 = (const float*)d_in[15];
    const float* pb2 = (const float*)d_in[16];
    const float* bn1g = (const float*)d_in[17];
    const float* bn1b = (const float*)d_in[18];
    const float* bn1m = (const float*)d_in[19];
    const float* bn1v = (const float*)d_in[20];
    const float* w1  = (const float*)d_in[21];
    const float* wb1 = (const float*)d_in[22];
    const float* bn2g = (const float*)d_in[23];
    const float* bn2b = (const float*)d_in[24];
    const float* bn2m = (const float*)d_in[25];
    const float* bn2v = (const float*)d_in[26];
    const float* w2  = (const float*)d_in[27];
    const float* wb2 = (const float*)d_in[28];

    int N = in_sizes[1] / 64;

    prep_kernel<<<1, 192>>>(Wq, bq, Wk, bk, Wv, bv,
                            pw1, pb1, pbng, pbnb, pbnm, pbnv, pw2, pb2,
                            bn1g, bn1b, bn1m, bn1v, w1, wb1,
                            bn2g, bn2b, bn2m, bn2v, w2, wb2);
    void* sp = nullptr;
    cudaGetSymbolAddress(&sp, g_stage);
    cudaMemcpyToSymbolAsync(c_P, sp, sizeof(CParams), 0,
                            cudaMemcpyDeviceToDevice, 0);

    proj3<<<(N + 63) / 64, 256>>>(x, N);
    attn2<<<(N + 7) / 8, 128>>>(p, idx, (float*)d_out, N);
}

// round 10
// speedup vs baseline: 1.3534x; 1.3534x over previous
#include <cuda_runtime.h>
#include <cuda_fp16.h>

#define NMAX 100000
#define EPSF 1e-5f

// q/k/v projection scratch in fp16 (device globals: allocation-free).
// Row = 32 half2 = 64 channels = 128 bytes (one L2/L1 line per row).
__device__ __half2 g_xq[NMAX * 32];
__device__ __half2 g_xk[NMAX * 32];
__device__ __half2 g_xv[NMAX * 32];

__device__ __forceinline__ float4 ldg_h4(const __half2* __restrict__ base,
                                         size_t row, int sub) {
    uint2 u = *(const uint2*)(base + row * 32 + sub * 2);
    __half2 a = *(__half2*)&u.x, b = *(__half2*)&u.y;
    float2 fa = __half22float2(a), fb = __half22float2(b);
    return make_float4(fa.x, fa.y, fb.x, fb.y);
}

// ---------------------------------------------------------------------------
// Folded constants, staged on device then copied into __constant__.
// ---------------------------------------------------------------------------
struct CParams {
    float4 w1[128];                         // w_w1 [o][4g..4g+3]
    float4 A[16];                           // bn1 scale folded
    float4 T0[16], T1[16], T2[16], TB[16];  // A*pw2 cols, A*pb2 + b1
    float4 R0[16], R1[16], R2[16], RB[16];  // raw pw2 cols, raw pb2
    float a2[8], c2f[8];                    // y = relu(a2*acc + c2f)
    float w2[64];
    float wb2[8];
    float fw1[9], fb1[3];                   // folded p-MLP layer1
    float pad[4];
};
__device__ CParams g_stage;
__constant__ CParams c_P;

__global__ void prep_kernel(
    const float* __restrict__ pw1, const float* __restrict__ pb1,
    const float* __restrict__ pbng, const float* __restrict__ pbnb,
    const float* __restrict__ pbnm, const float* __restrict__ pbnv,
    const float* __restrict__ pw2, const float* __restrict__ pb2,
    const float* __restrict__ bn1g, const float* __restrict__ bn1b,
    const float* __restrict__ bn1m, const float* __restrict__ bn1v,
    const float* __restrict__ w1,  const float* __restrict__ wb1,
    const float* __restrict__ bn2g, const float* __restrict__ bn2b,
    const float* __restrict__ bn2m, const float* __restrict__ bn2v,
    const float* __restrict__ w2,  const float* __restrict__ wb2)
{
    int t = threadIdx.x;  // 64 threads
    if (t < 64) {
        float a  = bn1g[t] * rsqrtf(bn1v[t] + EPSF);
        float b1 = bn1b[t] - bn1m[t] * a;
        float r0 = pw2[t * 3 + 0], r1 = pw2[t * 3 + 1], r2 = pw2[t * 3 + 2];
        float rb = pb2[t];
        ((float*)g_stage.A )[t] = a;
        ((float*)g_stage.T0)[t] = a * r0;
        ((float*)g_stage.T1)[t] = a * r1;
        ((float*)g_stage.T2)[t] = a * r2;
        ((float*)g_stage.TB)[t] = a * rb + b1;
        ((float*)g_stage.R0)[t] = r0;
        ((float*)g_stage.R1)[t] = r1;
        ((float*)g_stage.R2)[t] = r2;
        ((float*)g_stage.RB)[t] = rb;
        g_stage.w2[t] = w2[t];
    }
    for (int i = t; i < 512; i += 64) ((float*)g_stage.w1)[i] = w1[i];
    if (t < 8) {
        float a2 = bn2g[t] * rsqrtf(bn2v[t] + EPSF);
        g_stage.a2[t]  = a2;
        g_stage.c2f[t] = a2 * wb1[t] + (bn2b[t] - bn2m[t] * a2);
        g_stage.wb2[t] = wb2[t];
    }
    if (t < 3) {
        float pa = pbng[t] * rsqrtf(pbnv[t] + EPSF);
        g_stage.fw1[t * 3 + 0] = pa * pw1[t * 3 + 0];
        g_stage.fw1[t * 3 + 1] = pa * pw1[t * 3 + 1];
        g_stage.fw1[t * 3 + 2] = pa * pw1[t * 3 + 2];
        g_stage.fb1[t] = pa * pb1[t] + (pbnb[t] - pbnm[t] * pa);
    }
}

// ---------------------------------------------------------------------------
// Kernel A: q/k/v projection, fp16 output. Block = 64 points, specialized per
// q/k/v via blockIdx.y. Thread = (4 out channels, 4 points).
// ---------------------------------------------------------------------------
__global__ __launch_bounds__(256) void proj2(
    const float* __restrict__ x,
    const float* __restrict__ Wq, const float* __restrict__ bq,
    const float* __restrict__ Wk, const float* __restrict__ bk,
    const float* __restrict__ Wv, const float* __restrict__ bv,
    int N)
{
    const float* W; const float* b; __half2* dst;
    if (blockIdx.y == 0)      { W = Wq; b = bq; dst = g_xq; }
    else if (blockIdx.y == 1) { W = Wk; b = bk; dst = g_xk; }
    else                      { W = Wv; b = bv; dst = g_xv; }

    __shared__ __align__(16) float Wt[64 * 68];
    __shared__ __align__(16) float xs[64 * 64];
    int t = threadIdx.x;

    for (int i = t; i < 4096; i += 256) {
        int o = i >> 6, c = i & 63;
        Wt[c * 68 + o] = W[i];
    }
    int tile0 = blockIdx.x * 64;
    for (int i = t; i < 1024; i += 256) {
        int f = i * 4;
        int pl = f >> 6, c = f & 63;
        int pt = tile0 + pl; pt = (pt < N) ? pt : N - 1;
        *(float4*)&xs[f] = *(const float4*)&x[(size_t)pt * 64 + c];
    }
    __syncthreads();

    int og = t & 15, pg = t >> 4;
    int o0 = og * 4;
    float4 bias = *(const float4*)&b[o0];

    float acc[4][4];
    #pragma unroll
    for (int a = 0; a < 4; a++)
        #pragma unroll
        for (int bb = 0; bb < 4; bb++) acc[a][bb] = 0.f;

    #pragma unroll
    for (int c4 = 0; c4 < 16; c4++) {
        float4 wv[4];
        #pragma unroll
        for (int k = 0; k < 4; k++)
            wv[k] = *(const float4*)&Wt[(4 * c4 + k) * 68 + o0];
        #pragma unroll
        for (int pp = 0; pp < 4; pp++) {
            float4 x4 = *(const float4*)&xs[(pg * 4 + pp) * 64 + 4 * c4];
            acc[pp][0] = fmaf(x4.x, wv[0].x, fmaf(x4.y, wv[1].x, fmaf(x4.z, wv[2].x, fmaf(x4.w, wv[3].x, acc[pp][0]))));
            acc[pp][1] = fmaf(x4.x, wv[0].y, fmaf(x4.y, wv[1].y, fmaf(x4.z, wv[2].y, fmaf(x4.w, wv[3].y, acc[pp][1]))));
            acc[pp][2] = fmaf(x4.x, wv[0].z, fmaf(x4.y, wv[1].z, fmaf(x4.z, wv[2].z, fmaf(x4.w, wv[3].z, acc[pp][2]))));
            acc[pp][3] = fmaf(x4.x, wv[0].w, fmaf(x4.y, wv[1].w, fmaf(x4.z, wv[2].w, fmaf(x4.w, wv[3].w, acc[pp][3]))));
        }
    }
    #pragma unroll
    for (int pp = 0; pp < 4; pp++) {
        int pt = tile0 + pg * 4 + pp;
        if (pt < N) {
            __half2 h0 = __floats2half2_rn(acc[pp][0] + bias.x, acc[pp][1] + bias.y);
            __half2 h1 = __floats2half2_rn(acc[pp][2] + bias.z, acc[pp][3] + bias.w);
            uint2 st;
            st.x = *(unsigned int*)&h0;
            st.y = *(unsigned int*)&h1;
            *(uint2*)(dst + (size_t)pt * 32 + og * 2) = st;
        }
    }
}

// ---------------------------------------------------------------------------
// Kernel B: fused attention. Block = 8 points, 128 threads, warp-local.
// Phase 2 uses the softmax identity: since sum_j wex_j = 1,
//   sum_j (xv + pw2.h_j + pb2)_c * wex_j[u]
// = sum_j xv_c*wex_j[u] + pw2_c . H[u] + pb2_c,  H[u] = sum_j h_j*wex_j[u].
// ---------------------------------------------------------------------------
__global__ __launch_bounds__(128) void attn2(
    const float* __restrict__ p, const int* __restrict__ idx,
    float* __restrict__ out, int N)
{
    __shared__ __align__(16) float4 vbuf[8][16][16];
    __shared__ __align__(16) float  wex[8][16][12];
    __shared__ __align__(16) float  Hs[8][3][8];
    __shared__ float hs[8][16][4];
    __shared__ int   idxs[8][16];
    __shared__ float pns[8][4];

    int t = threadIdx.x, lane = t & 31, wid = t >> 5;
    int n0 = blockIdx.x * 8;

    int lpA = t >> 4, sub = t & 15;
    int nA  = n0 + lpA;
    int nAc = (nA < N) ? nA : N - 1;

    // prologue: indices, center coords, h-MLP
    int id0 = idx[(size_t)nAc * 16 + sub];
    id0 = (id0 < 0) ? 0 : ((id0 >= N) ? N - 1 : id0);
    idxs[lpA][sub] = id0;
    if (lane < 6) {
        int pp = wid * 2 + lane / 3, d = lane % 3;
        int np = n0 + pp; np = (np < N) ? np : N - 1;
        pns[pp][d] = p[(size_t)np * 3 + d];
    }
    __syncwarp();
    {
        float prx = p[(size_t)id0 * 3 + 0] - pns[lpA][0];
        float pry = p[(size_t)id0 * 3 + 1] - pns[lpA][1];
        float prz = p[(size_t)id0 * 3 + 2] - pns[lpA][2];
        hs[lpA][sub][0] = fmaxf(fmaf(prx, c_P.fw1[0], fmaf(pry, c_P.fw1[1], fmaf(prz, c_P.fw1[2], c_P.fb1[0]))), 0.f);
        hs[lpA][sub][1] = fmaxf(fmaf(prx, c_P.fw1[3], fmaf(pry, c_P.fw1[4], fmaf(prz, c_P.fw1[5], c_P.fb1[1]))), 0.f);
        hs[lpA][sub][2] = fmaxf(fmaf(prx, c_P.fw1[6], fmaf(pry, c_P.fw1[7], fmaf(prz, c_P.fw1[8], c_P.fb1[2]))), 0.f);
    }
    float4 Ac = c_P.A[sub];
    float4 T0 = c_P.T0[sub], T1 = c_P.T1[sub], T2 = c_P.T2[sub];
    float4 TBc = c_P.TB[sub];
    float4 xq4 = ldg_h4(g_xq, (size_t)nAc, sub);
    float4 TBm = make_float4(TBc.x - Ac.x * xq4.x, TBc.y - Ac.y * xq4.y,
                             TBc.z - Ac.z * xq4.z, TBc.w - Ac.w * xq4.w);
    __syncwarp();

    // ---- Phase A: v = relu(A*xk + T.h + TBm) -> swizzled vbuf --------------
    #pragma unroll
    for (int j = 0; j < 16; j++) {
        int id = idxs[lpA][j];
        float h0 = hs[lpA][j][0], h1 = hs[lpA][j][1], h2 = hs[lpA][j][2];
        float4 xk4 = ldg_h4(g_xk, (size_t)id, sub);
        float4 v;
        v.x = fmaxf(fmaf(Ac.x, xk4.x, fmaf(T2.x, h2, fmaf(T1.x, h1, fmaf(T0.x, h0, TBm.x)))), 0.f);
        v.y = fmaxf(fmaf(Ac.y, xk4.y, fmaf(T2.y, h2, fmaf(T1.y, h1, fmaf(T0.y, h0, TBm.y)))), 0.f);
        v.z = fmaxf(fmaf(Ac.z, xk4.z, fmaf(T2.z, h2, fmaf(T1.z, h1, fmaf(T0.z, h0, TBm.z)))), 0.f);
        v.w = fmaxf(fmaf(Ac.w, xk4.w, fmaf(T2.w, h2, fmaf(T1.w, h1, fmaf(T0.w, h0, TBm.w)))), 0.f);
        vbuf[lpA][j][(sub + j) & 15] = v;
    }
    __syncwarp();

    // ---- Phase B: 64->8 projection + BN2 + w2 + softmax --------------------
    int lpB = wid * 2 + (lane >> 4), jj = lane & 15;
    float acc[8];
    #pragma unroll
    for (int o = 0; o < 8; o++) acc[o] = 0.f;
    #pragma unroll
    for (int g = 0; g < 16; g++) {
        float4 v4 = vbuf[lpB][jj][(g + jj) & 15];
        #pragma unroll
        for (int o = 0; o < 8; o++) {
            float4 w = c_P.w1[o * 16 + g];
            acc[o] = fmaf(w.x, v4.x, fmaf(w.y, v4.y, fmaf(w.z, v4.z, fmaf(w.w, v4.w, acc[o]))));
        }
    }
    float y[8], z[8];
    #pragma unroll
    for (int o = 0; o < 8; o++)
        y[o] = fmaxf(fmaf(c_P.a2[o], acc[o], c_P.c2f[o]), 0.f);
    #pragma unroll
    for (int u = 0; u < 8; u++) {
        float s = c_P.wb2[u];
        #pragma unroll
        for (int o = 0; o < 8; o++) s = fmaf(y[o], c_P.w2[u * 8 + o], s);
        z[u] = s;
    }
    float e[8];
    #pragma unroll
    for (int u = 0; u < 8; u++) {
        float m = z[u];
        m = fmaxf(m, __shfl_xor_sync(0xffffffffu, m, 1));
        m = fmaxf(m, __shfl_xor_sync(0xffffffffu, m, 2));
        m = fmaxf(m, __shfl_xor_sync(0xffffffffu, m, 4));
        m = fmaxf(m, __shfl_xor_sync(0xffffffffu, m, 8));
        float ev = __expf(z[u] - m);
        float s = ev;
        s += __shfl_xor_sync(0xffffffffu, s, 1);
        s += __shfl_xor_sync(0xffffffffu, s, 2);
        s += __shfl_xor_sync(0xffffffffu, s, 4);
        s += __shfl_xor_sync(0xffffffffu, s, 8);
        e[u] = ev * __frcp_rn(s);
    }
    *(float4*)&wex[lpB][jj][0] = make_float4(e[0], e[1], e[2], e[3]);
    *(float4*)&wex[lpB][jj][4] = make_float4(e[4], e[5], e[6], e[7]);
    __syncwarp();

    // ---- H[u] = sum_j h_j * wex_j[u]  (per point, 3x8 values) --------------
    if (sub < 8) {
        float H0 = 0.f, H1 = 0.f, H2 = 0.f;
        #pragma unroll
        for (int j = 0; j < 16; j++) {
            float w = wex[lpA][j][sub];
            H0 = fmaf(hs[lpA][j][0], w, H0);
            H1 = fmaf(hs[lpA][j][1], w, H1);
            H2 = fmaf(hs[lpA][j][2], w, H2);
        }
        Hs[lpA][0][sub] = H0;
        Hs[lpA][1][sub] = H1;
        Hs[lpA][2][sub] = H2;
    }
    __syncwarp();

    // ---- Phase 2: out_c = pw2_c.H[u] + pb2_c + sum_j xv_jc * wex_j[u] ------
    float4 q0 = c_P.R0[sub], q1 = c_P.R1[sub], q2 = c_P.R2[sub], qb = c_P.RB[sub];
    int u0 = (sub & 1) * 4;
    float4 H0v = *(const float4*)&Hs[lpA][0][u0];
    float4 H1v = *(const float4*)&Hs[lpA][1][u0];
    float4 H2v = *(const float4*)&Hs[lpA][2][u0];
    float bx = fmaf(q0.x, H0v.x, fmaf(q1.x, H1v.x, fmaf(q2.x, H2v.x, qb.x)));
    float by = fmaf(q0.y, H0v.y, fmaf(q1.y, H1v.y, fmaf(q2.y, H2v.y, qb.y)));
    float bz = fmaf(q0.z, H0v.z, fmaf(q1.z, H1v.z, fmaf(q2.z, H2v.z, qb.z)));
    float bw = fmaf(q0.w, H0v.w, fmaf(q1.w, H1v.w, fmaf(q2.w, H2v.w, qb.w)));

    float ox = 0.f, oy = 0.f, oz = 0.f, ow = 0.f;
    #pragma unroll
    for (int j = 0; j < 16; j++) {
        int id = idxs[lpA][j];
        float4 xv4 = ldg_h4(g_xv, (size_t)id, sub);
        float4 wn4 = *(const float4*)&wex[lpA][j][u0];
        ox = fmaf(xv4.x, wn4.x, ox);
        oy = fmaf(xv4.y, wn4.y, oy);
        oz = fmaf(xv4.z, wn4.z, oz);
        ow = fmaf(xv4.w, wn4.w, ow);
    }
    if (nA < N)
        *(float4*)&out[(size_t)nA * 64 + sub * 4] =
            make_float4(ox + bx, oy + by, oz + bz, ow + bw);
}

// ---------------------------------------------------------------------------
extern "C" void kernel_launch(void* const* d_in, const int* in_sizes, int n_in,
                              void* d_out, int out_size)
{
    const float* p   = (const float*)d_in[0];
    const float* x   = (const float*)d_in[1];
    const int* idx   = (const int*)d_in[2];
    const float* Wq  = (const float*)d_in[3];
    const float* bq  = (const float*)d_in[4];
    const float* Wk  = (const float*)d_in[5];
    const float* bk  = (const float*)d_in[6];
    const float* Wv  = (const float*)d_in[7];
    const float* bv  = (const float*)d_in[8];
    const float* pw1 = (const float*)d_in[9];
    const float* pb1 = (const float*)d_in[10];
    const float* pbng = (const float*)d_in[11];
    const float* pbnb = (const float*)d_in[12];
    const float* pbnm = (const float*)d_in[13];
    const float* pbnv = (const float*)d_in[14];
    const float* pw2 = (const float*)d_in[15];
    const float* pb2 = (const float*)d_in[16];
    const float* bn1g = (const float*)d_in[17];
    const float* bn1b = (const float*)d_in[18];
    const float* bn1m = (const float*)d_in[19];
    const float* bn1v = (const float*)d_in[20];
    const float* w1  = (const float*)d_in[21];
    const float* wb1 = (const float*)d_in[22];
    const float* bn2g = (const float*)d_in[23];
    const float* bn2b = (const float*)d_in[24];
    const float* bn2m = (const float*)d_in[25];
    const float* bn2v = (const float*)d_in[26];
    const float* w2  = (const float*)d_in[27];
    const float* wb2 = (const float*)d_in[28];

    int N = in_sizes[1] / 64;

    prep_kernel<<<1, 64>>>(pw1, pb1, pbng, pbnb, pbnm, pbnv, pw2, pb2,
                           bn1g, bn1b, bn1m, bn1v, w1, wb1,
                           bn2g, bn2b, bn2m, bn2v, w2, wb2);
    void* sp = nullptr;
    cudaGetSymbolAddress(&sp, g_stage);
    cudaMemcpyToSymbolAsync(c_P, sp, sizeof(CParams), 0,
                            cudaMemcpyDeviceToDevice, 0);

    dim3 pgrid((N + 63) / 64, 3);
    proj2<<<pgrid, 256>>>(x, Wq, bq, Wk, bk, Wv, bv, N);
    attn2<<<(N + 7) / 8, 128>>>(p, idx, (float*)d_out, N);
}